// round 4
// baseline (speedup 1.0000x reference)
#include <cuda_runtime.h>
#include <math.h>

#define NN 100000
#define NE 1600000
#define HD 32

// ---- scratch (__device__ globals: no allocations allowed) ----
__device__ float g_emb_pre[NN * HD];   // pre-batchnorm node embedding
__device__ float g_emb[NN * HD];       // post-batchnorm node embedding
__device__ float g_q[NN * HD];         // emb @ W_bot           (per-src term)
__device__ float g_pb[NN * HD];        // emb @ (W_top-W_bot)+b (per-dst term)
__device__ float g_maxq[NN * HD];      // segment max of q over incoming edges
__device__ float g_stats[4 * HD];      // sum1, sq1, sum2, sq2
__device__ float g_bn[4 * HD];         // s1, t1, s2, t2  (y = x*s + t)

__device__ __forceinline__ float eluf(float x) { return x > 0.f ? x : expm1f(x); }

// ---- K0: zero BN accumulators (must be re-zeroed every graph replay) ----
__global__ void k_zero_stats() {
    int t = threadIdx.x;
    if (t < 4 * HD) g_stats[t] = 0.f;
}

// ---- K1: node feature encoder -> g_emb_pre ----
__global__ void __launch_bounds__(256) k_embed(
    const float* __restrict__ x_cont, const int* __restrict__ x_cat,
    const float* __restrict__ W_cont, const float* __restrict__ b_cont,
    const float* __restrict__ T_chrg, const float* __restrict__ T_pdg,
    const float* __restrict__ T_pv,
    const float* __restrict__ W_cat,  const float* __restrict__ b_cat,
    const float* __restrict__ W_enc,  const float* __restrict__ b_enc)
{
    __shared__ float sWc[96], sbc[16], sTc[24], sTp[56], sTv[64];
    __shared__ float sWk[384], sbk[16], sWe[1024], sbe[32];
    int tid = threadIdx.x;
    for (int i = tid; i < 96;   i += 256) sWc[i] = W_cont[i];
    for (int i = tid; i < 16;   i += 256) sbc[i] = b_cont[i];
    for (int i = tid; i < 24;   i += 256) sTc[i] = T_chrg[i];
    for (int i = tid; i < 56;   i += 256) sTp[i] = T_pdg[i];
    for (int i = tid; i < 64;   i += 256) sTv[i] = T_pv[i];
    for (int i = tid; i < 384;  i += 256) sWk[i] = W_cat[i];
    for (int i = tid; i < 16;   i += 256) sbk[i] = b_cat[i];
    for (int i = tid; i < 1024; i += 256) sWe[i] = W_enc[i];
    for (int i = tid; i < 32;   i += 256) sbe[i] = b_enc[i];
    __syncthreads();

    int n = blockIdx.x * 256 + tid;
    if (n >= NN) return;

    // continuous branch: elu(x_cont @ W_cont + b)
    float c[6];
    #pragma unroll
    for (int k = 0; k < 6; k++) c[k] = x_cont[n * 6 + k];
    float h1[16];
    #pragma unroll
    for (int j = 0; j < 16; j++) {
        float a = sbc[j];
        #pragma unroll
        for (int k = 0; k < 6; k++) a += c[k] * sWc[k * 16 + j];
        h1[j] = eluf(a);
    }

    // categorical branch
    int pdg_s = x_cat[n * 3 + 0];
    int chrg  = x_cat[n * 3 + 1];
    int pv    = x_cat[n * 3 + 2];
    int ap = pdg_s < 0 ? -pdg_s : pdg_s;
    int pi;
    switch (ap) {
        case 1:   pi = 0; break;
        case 2:   pi = 1; break;
        case 11:  pi = 2; break;
        case 13:  pi = 3; break;
        case 22:  pi = 4; break;
        case 130: pi = 5; break;
        default:  pi = 6; break;  // 211
    }
    float cat24[24];
    #pragma unroll
    for (int j = 0; j < 8; j++) {
        cat24[j]      = sTc[(chrg + 1) * 8 + j];
        cat24[8 + j]  = sTp[pi * 8 + j];
        cat24[16 + j] = sTv[pv * 8 + j];
    }
    float h2[16];
    #pragma unroll
    for (int j = 0; j < 16; j++) {
        float a = sbk[j];
        #pragma unroll
        for (int k = 0; k < 24; k++) a += cat24[k] * sWk[k * 16 + j];
        h2[j] = eluf(a);
    }

    // encoder: elu([emb_cat, emb_cont] @ W_enc + b_enc)
    float4* dst = (float4*)(g_emb_pre + (size_t)n * HD);
    #pragma unroll
    for (int jv = 0; jv < 8; jv++) {
        float o[4];
        #pragma unroll
        for (int u = 0; u < 4; u++) {
            int j = jv * 4 + u;
            float a = sbe[j];
            #pragma unroll
            for (int k = 0; k < 16; k++) a += h2[k] * sWe[k * 32 + j];
            #pragma unroll
            for (int k = 0; k < 16; k++) a += h1[k] * sWe[(16 + k) * 32 + j];
            o[u] = eluf(a);
        }
        dst[jv] = make_float4(o[0], o[1], o[2], o[3]);
    }
}

// ---- K1b/K5: per-feature column stats (coalesced; feature = gid & 31) ----
// mode 0: source is g_emb_pre            -> sum1/sq1
// mode 1: source is agg = pb+maxq (or 0) -> sum2/sq2
__global__ void __launch_bounds__(256) k_col_stats(int mode) {
    float acc_s = 0.f, acc_q = 0.f;
    long stride = (long)gridDim.x * 256;
    for (long i = (long)blockIdx.x * 256 + threadIdx.x; i < (long)NN * HD; i += stride) {
        float v;
        if (mode == 0) {
            v = g_emb_pre[i];
        } else {
            float m = g_maxq[i];
            v = (__float_as_uint(m) == 0xff800000u) ? 0.f : (g_pb[i] + m);
        }
        acc_s += v;
        acc_q += v * v;
    }
    __shared__ float ss[256], sq[256];
    int t = threadIdx.x;
    ss[t] = acc_s; sq[t] = acc_q;
    __syncthreads();
    if (t < 32) {
        #pragma unroll
        for (int w = 1; w < 8; w++) { acc_s += ss[t + 32 * w]; acc_q += sq[t + 32 * w]; }
        float* base = g_stats + mode * 2 * HD;
        atomicAdd(&base[t], acc_s);
        atomicAdd(&base[HD + t], acc_q);
    }
}

// ---- K2/K6: fold batchnorm into affine y = x*s + t ----
__global__ void k_bn_params(const float* __restrict__ gamma,
                            const float* __restrict__ beta, int mode) {
    int t = threadIdx.x;
    if (t >= HD) return;
    const float invN = 1.f / (float)NN;
    float mu  = g_stats[mode * 2 * HD + t] * invN;
    float var = g_stats[mode * 2 * HD + HD + t] * invN - mu * mu;
    float s = gamma[t] * rsqrtf(var + 1e-5f);
    g_bn[mode * 2 * HD + t]      = s;
    g_bn[mode * 2 * HD + HD + t] = beta[t] - mu * s;
}

// ---- K3: apply BN1, compute q = emb@W_bot and pb = emb@(W_top-W_bot)+b_msg,
//          init maxq to -inf ----
__global__ void __launch_bounds__(256) k_pq(const float* __restrict__ W_msg,
                                            const float* __restrict__ b_msg) {
    __shared__ float sA[1024], sB[1024], sbm[32], ss1[32], st1[32];
    int tid = threadIdx.x;
    for (int i = tid; i < 1024; i += 256) {
        float top = W_msg[i];
        float bot = W_msg[1024 + i];
        sA[i] = top - bot;
        sB[i] = bot;
    }
    if (tid < 32) { sbm[tid] = b_msg[tid]; ss1[tid] = g_bn[tid]; st1[tid] = g_bn[HD + tid]; }
    __syncthreads();

    int n = blockIdx.x * 256 + tid;
    if (n >= NN) return;

    float e[32];
    const float4* src = (const float4*)(g_emb_pre + (size_t)n * HD);
    #pragma unroll
    for (int v = 0; v < 8; v++) {
        float4 f = src[v];
        e[4 * v + 0] = f.x; e[4 * v + 1] = f.y; e[4 * v + 2] = f.z; e[4 * v + 3] = f.w;
    }
    #pragma unroll
    for (int j = 0; j < 32; j++) e[j] = fmaf(e[j], ss1[j], st1[j]);

    float4* de = (float4*)(g_emb + (size_t)n * HD);
    #pragma unroll
    for (int v = 0; v < 8; v++)
        de[v] = make_float4(e[4 * v], e[4 * v + 1], e[4 * v + 2], e[4 * v + 3]);

    float p[32], q[32];
    #pragma unroll
    for (int j = 0; j < 32; j++) { p[j] = sbm[j]; q[j] = 0.f; }
    #pragma unroll 4
    for (int k = 0; k < 32; k++) {
        float ek = e[k];
        #pragma unroll
        for (int j = 0; j < 32; j++) {
            p[j] = fmaf(ek, sA[k * 32 + j], p[j]);
            q[j] = fmaf(ek, sB[k * 32 + j], q[j]);
        }
    }

    float4* dq = (float4*)(g_q    + (size_t)n * HD);
    float4* dp = (float4*)(g_pb   + (size_t)n * HD);
    float4* dm = (float4*)(g_maxq + (size_t)n * HD);
    float ninf = __int_as_float((int)0xff800000);
    float4 nf4 = make_float4(ninf, ninf, ninf, ninf);
    #pragma unroll
    for (int v = 0; v < 8; v++) {
        dq[v] = make_float4(q[4 * v], q[4 * v + 1], q[4 * v + 2], q[4 * v + 3]);
        dp[v] = make_float4(p[4 * v], p[4 * v + 1], p[4 * v + 2], p[4 * v + 3]);
        dm[v] = nf4;
    }
}

// ---- K4: edge segment-max. warp = 1 edge, lane = feature.
//      gather q[src] (coalesced 128B) + one float atomicMax each. ----
__global__ void __launch_bounds__(256) k_edges(const int* __restrict__ ei) {
    long gid = (long)blockIdx.x * 256 + threadIdx.x;
    if (gid >= (long)NE * HD) return;
    int e = (int)(gid >> 5);
    int h = (int)(gid & 31);
    int src = __ldg(&ei[e]);
    int dst = __ldg(&ei[NE + e]);
    float v = __ldg(&g_q[(size_t)src * HD + h]);
    if (__float_as_uint(v) == 0x80000000u) v = 0.f;   // -0 would break the int trick
    float* addr = &g_maxq[(size_t)dst * HD + h];
    // order-independent float max via signed/unsigned split (init = -inf)
    if (v >= 0.f) atomicMax((int*)addr, __float_as_int(v));
    else          atomicMin((unsigned int*)addr, __float_as_uint(v));
}

// ---- K7: residual + BN2 + output MLP ----
__global__ void __launch_bounds__(256) k_out(
    const float* __restrict__ W_out1, const float* __restrict__ b_out1,
    const float* __restrict__ W_out2, const float* __restrict__ b_out2,
    float* __restrict__ out)
{
    __shared__ float sW1[512], sb1[16], sW2[16], ss2[32], st2[32];
    __shared__ float sb2;
    int tid = threadIdx.x;
    for (int i = tid; i < 512; i += 256) sW1[i] = W_out1[i];
    if (tid < 16) { sb1[tid] = b_out1[tid]; sW2[tid] = W_out2[tid]; }
    if (tid < 32) { ss2[tid] = g_bn[2 * HD + tid]; st2[tid] = g_bn[3 * HD + tid]; }
    if (tid == 0) sb2 = b_out2[0];
    __syncthreads();

    int n = blockIdx.x * 256 + tid;
    if (n >= NN) return;

    float x[32];
    const float4* fe = (const float4*)(g_emb  + (size_t)n * HD);
    const float4* fm = (const float4*)(g_maxq + (size_t)n * HD);
    const float4* fp = (const float4*)(g_pb   + (size_t)n * HD);
    #pragma unroll
    for (int v = 0; v < 8; v++) {
        float4 em = fe[v], mx = fm[v], pb = fp[v];
        float m4[4] = {mx.x, mx.y, mx.z, mx.w};
        float p4[4] = {pb.x, pb.y, pb.z, pb.w};
        float e4[4] = {em.x, em.y, em.z, em.w};
        #pragma unroll
        for (int u = 0; u < 4; u++) {
            int j = v * 4 + u;
            float a = (__float_as_uint(m4[u]) == 0xff800000u) ? 0.f : (p4[u] + m4[u]);
            x[j] = e4[u] + fmaf(a, ss2[j], st2[j]);
        }
    }

    float h[16];
    #pragma unroll
    for (int j = 0; j < 16; j++) {
        float a = sb1[j];
        #pragma unroll
        for (int k = 0; k < 32; k++) a = fmaf(x[k], sW1[k * 16 + j], a);
        h[j] = eluf(a);
    }
    float o = sb2;
    #pragma unroll
    for (int k = 0; k < 16; k++) o = fmaf(h[k], sW2[k], o);
    out[n] = o;
}

extern "C" void kernel_launch(void* const* d_in, const int* in_sizes, int n_in,
                              void* d_out, int out_size) {
    const float* x_cont  = (const float*)d_in[0];
    const int*   x_cat   = (const int*)  d_in[1];
    const int*   ei      = (const int*)  d_in[2];
    /* d_in[3] = batch (all zeros, unused) */
    const float* W_cont  = (const float*)d_in[4];
    const float* b_cont  = (const float*)d_in[5];
    const float* T_chrg  = (const float*)d_in[6];
    const float* T_pdg   = (const float*)d_in[7];
    const float* T_pv    = (const float*)d_in[8];
    const float* W_cat   = (const float*)d_in[9];
    const float* b_cat   = (const float*)d_in[10];
    const float* W_enc   = (const float*)d_in[11];
    const float* b_enc   = (const float*)d_in[12];
    const float* g_all   = (const float*)d_in[13];
    const float* be_all  = (const float*)d_in[14];
    const float* W_msg   = (const float*)d_in[15];
    const float* b_msg   = (const float*)d_in[16];
    const float* g_conv  = (const float*)d_in[17];
    const float* be_conv = (const float*)d_in[18];
    const float* W_out1  = (const float*)d_in[19];
    const float* b_out1  = (const float*)d_in[20];
    const float* W_out2  = (const float*)d_in[21];
    const float* b_out2  = (const float*)d_in[22];
    float* out = (float*)d_out;

    const int nb = (NN + 255) / 256;                       // 391
    const int eb = (int)(((long)NE * HD + 255) / 256);     // 200000

    k_zero_stats<<<1, 128>>>();
    k_embed<<<nb, 256>>>(x_cont, x_cat, W_cont, b_cont, T_chrg, T_pdg, T_pv,
                         W_cat, b_cat, W_enc, b_enc);
    k_col_stats<<<132, 256>>>(0);
    k_bn_params<<<1, 32>>>(g_all, be_all, 0);
    k_pq<<<nb, 256>>>(W_msg, b_msg);
    k_edges<<<eb, 256>>>(ei);
    k_col_stats<<<132, 256>>>(1);
    k_bn_params<<<1, 32>>>(g_conv, be_conv, 1);
    k_out<<<nb, 256>>>(W_out1, b_out1, W_out2, b_out2, out);
}